// round 14
// baseline (speedup 1.0000x reference)
#include <cuda_runtime.h>
#include <math.h>
#include <stdint.h>

// ---------------- problem constants ----------------
constexpr int   B_  = 8;
constexpr int   T_  = 2048;
constexpr int   D_  = 1024;
constexpr int   H_  = 16;
constexpr int   HD_ = 64;
constexpr size_t BTD = (size_t)B_ * T_ * D_;   // 16,777,216
constexpr size_t BT  = (size_t)B_ * T_;        // 16,384
constexpr float LOG_W_SCALE = -0.6065306597126334f;
constexpr float GN_EPS = (float)HD_ * 1e-5f;

// ---------------- scratch pool ----------------
constexpr size_t N_SLOTS = 17;
constexpr size_t T1_OFF = N_SLOTS * BTD;
constexpr size_t T2_OFF = T1_OFF + BT * 64;
constexpr size_t T3_OFF = T2_OFF + BT * 64;
constexpr size_t T4_OFF = T3_OFF + BT * 32;
constexpr size_t WT_OFF  = T4_OFF + BT * 160;
constexpr size_t WRT_OFF = WT_OFF;
constexpr size_t WKT_OFF = WRT_OFF + (size_t)D_ * D_;
constexpr size_t WVT_OFF = WKT_OFF + (size_t)D_ * D_;
constexpr size_t WOT_OFF = WVT_OFF + (size_t)D_ * D_;
constexpr size_t W1T_OFF = WOT_OFF + (size_t)D_ * D_;
constexpr size_t W2T_OFF = W1T_OFF + (size_t)64 * 1024;
constexpr size_t A1T_OFF = W2T_OFF + (size_t)64 * 1024;
constexpr size_t A2T_OFF = A1T_OFF + (size_t)64 * 1024;
constexpr size_t V1T_OFF = A2T_OFF + (size_t)64 * 1024;
constexpr size_t V2T_OFF = V1T_OFF + (size_t)32 * 1024;
constexpr size_t G1T_OFF = V2T_OFF + (size_t)32 * 1024;
constexpr size_t G2T_OFF = G1T_OFF + (size_t)160 * 1024;
constexpr size_t SCRATCH_FLOATS = G2T_OFF + (size_t)160 * 1024;

__device__ float g_scratch[SCRATCH_FLOATS];

// ---------------- helpers ----------------
__device__ __forceinline__ uint32_t tf32bits(float x) {
    uint32_t y;
    asm("cvt.rna.tf32.f32 %0, %1;" : "=r"(y) : "f"(x));
    return y;
}
__device__ __forceinline__ float tf32f(float x) {
    return __uint_as_float(tf32bits(x));
}
__device__ __forceinline__ void mma_tf32(float& c0, float& c1, float& c2, float& c3,
                                         uint32_t a0, uint32_t a1, uint32_t a2, uint32_t a3,
                                         uint32_t b0, uint32_t b1) {
    asm volatile(
        "mma.sync.aligned.m16n8k8.row.col.f32.tf32.tf32.f32 "
        "{%0,%1,%2,%3}, {%4,%5,%6,%7}, {%8,%9}, {%0,%1,%2,%3};"
        : "+f"(c0), "+f"(c1), "+f"(c2), "+f"(c3)
        : "r"(a0), "r"(a1), "r"(a2), "r"(a3), "r"(b0), "r"(b1));
}
__device__ __forceinline__ void ldsm_x4(uint32_t& r0, uint32_t& r1, uint32_t& r2,
                                        uint32_t& r3, uint32_t addr) {
    asm volatile("ldmatrix.sync.aligned.m8n8.x4.shared.b16 {%0,%1,%2,%3}, [%4];"
                 : "=r"(r0), "=r"(r1), "=r"(r2), "=r"(r3) : "r"(addr));
}
__device__ __forceinline__ void ldsm_x2(uint32_t& r0, uint32_t& r1, uint32_t addr) {
    asm volatile("ldmatrix.sync.aligned.m8n8.x2.shared.b16 {%0,%1}, [%2];"
                 : "=r"(r0), "=r"(r1) : "r"(addr));
}
__device__ __forceinline__ uint32_t smem_u32(const void* p) {
    uint32_t a;
    asm("{ .reg .u64 t; cvta.to.shared.u64 t, %1; cvt.u32.u64 %0, t; }"
        : "=r"(a) : "l"(p));
    return a;
}
__device__ __forceinline__ void cp_async16(uint32_t saddr, const void* gptr) {
    asm volatile("cp.async.cg.shared.global [%0], [%1], 16;"
                 :: "r"(saddr), "l"(gptr) : "memory");
}
__device__ __forceinline__ void cp_async16z(uint32_t saddr, const void* gptr, int valid) {
    asm volatile("cp.async.cg.shared.global [%0], [%1], 16, %2;"
                 :: "r"(saddr), "l"(gptr), "r"(valid ? 16 : 0) : "memory");
}
__device__ __forceinline__ void cp_commit() {
    asm volatile("cp.async.commit_group;" ::: "memory");
}
__device__ __forceinline__ void cp_wait1() {
    asm volatile("cp.async.wait_group 1;" ::: "memory");
}
__device__ __forceinline__ void cp_wait6() {
    asm volatile("cp.async.wait_group 6;" ::: "memory");
}
__device__ __forceinline__ float apply_epi(float f, int mode,
                                           const float* __restrict__ bias, int colg) {
    if (mode == 1) {
        f = tanhf(f);
    } else if (mode == 2) {
        float s = 1.0f / (1.0f + expf(-(__ldg(&bias[colg]) + f)));
        f = expf(LOG_W_SCALE * s);
    } else if (mode == 3) {
        f = 1.0f / (1.0f + expf(-(__ldg(&bias[colg]) + f)));
    } else if (mode == 4) {
        f = 1.0f / (1.0f + expf(-f));
    }
    return f;
}

// ---------------- kernel: token-shift mixes, float4, tf32-rounded ----------------
__global__ void mix_kernel(const float4* __restrict__ x4,
                           const float4* __restrict__ xx4,
                           float4* __restrict__ out /* 6 x BTD/4 */) {
    size_t idx4 = (size_t)blockIdx.x * blockDim.x + threadIdx.x;
    if (idx4 >= BTD / 4) return;
    int d4 = (int)(idx4 & (D_ / 4 - 1));
    int t = (int)((idx4 >> 8) & (T_ - 1));
    float4 xc = x4[idx4];
    float4 xp = make_float4(0.f, 0.f, 0.f, 0.f);
    if (t > 0) xp = x4[idx4 - D_ / 4];
    float dx = xp.x - xc.x, dy = xp.y - xc.y, dz = xp.z - xc.z, dw = xp.w - xc.w;
#pragma unroll
    for (int j = 0; j < 6; j++) {
        float4 cf = __ldg(&xx4[j * (D_ / 4) + d4]);
        float4 r;
        r.x = tf32f(xc.x + dx * cf.x);
        r.y = tf32f(xc.y + dy * cf.y);
        r.z = tf32f(xc.z + dz * cf.z);
        r.w = tf32f(xc.w + dw * cf.w);
        out[(size_t)j * (BTD / 4) + idx4] = r;
    }
}

// ---------------- transpose kernel: in[K,N] -> out[N,K], tf32-rounded ----------------
__global__ void transpose_kernel(const float* __restrict__ in, float* __restrict__ out,
                                 int K, int N) {
    __shared__ float tile[32][33];
    int n0 = blockIdx.x * 32, k0 = blockIdx.y * 32;
    int tx = threadIdx.x, ty = threadIdx.y;  // 32 x 8
#pragma unroll
    for (int i = 0; i < 32; i += 8) {
        int k = k0 + ty + i, n = n0 + tx;
        if (k < K && n < N) tile[ty + i][tx] = tf32f(in[(size_t)k * N + n]);
    }
    __syncthreads();
#pragma unroll
    for (int i = 0; i < 32; i += 8) {
        int n = n0 + ty + i, k = k0 + tx;
        if (n < N && k < K) out[(size_t)n * K + k] = tile[tx][ty + i];
    }
}

// ---------------- tf32 GEMM: 3-stage cp.async, swizzled smem, 1 barrier/tile ----------------
constexpr int STAGE_FLOATS = 128 * 32;
constexpr unsigned GEMM_SMEM = 3 * 2 * STAGE_FLOATS * 4;     // 98304 B
__global__ __launch_bounds__(256)
void tgemm_kernel(const float* __restrict__ A, const float* __restrict__ Bt,
                  float* __restrict__ C, int M, int N, int K,
                  int mode, const float* __restrict__ bias, int rnd) {
    extern __shared__ float dsm[];
    uint32_t smem_base = smem_u32(dsm);

    int tid = threadIdx.x;
    int wid = tid >> 5, lane = tid & 31;
    int warp_m = wid >> 2;
    int warp_n = wid & 3;
    int gid = lane >> 2;
    int tig = lane & 3;
    int block_row = blockIdx.y * 128;
    int block_col = blockIdx.x * 128;

    float acc[4][4][4];
#pragma unroll
    for (int mt = 0; mt < 4; mt++)
#pragma unroll
        for (int nt = 0; nt < 4; nt++)
#pragma unroll
            for (int q = 0; q < 4; q++) acc[mt][nt][q] = 0.0f;

    int lr[4], lcc[4];
    uint32_t sdstA[4], sdstB[4];
#pragma unroll
    for (int i = 0; i < 4; i++) {
        int f4 = tid + i * 256;
        lr[i] = f4 >> 3;
        lcc[i] = f4 & 7;
        uint32_t sw = (uint32_t)(lcc[i] ^ (lr[i] & 7));
        sdstA[i] = (uint32_t)(lr[i] * 128 + sw * 16);
        sdstB[i] = sdstA[i] + STAGE_FLOATS * 4;
    }

    int ntiles = K >> 5;

    auto issue_tile = [&](int kt, int stage) {
        uint32_t sb = smem_base + (uint32_t)(stage * 2 * STAGE_FLOATS * 4);
        int k0 = kt << 5;
#pragma unroll
        for (int i = 0; i < 4; i++) {
            const float* ga = A + (size_t)(block_row + lr[i]) * K + k0 + lcc[i] * 4;
            cp_async16(sb + sdstA[i], ga);
            int rg = block_col + lr[i];
            const float* gb = Bt + (size_t)(rg < N ? rg : 0) * K + k0 + lcc[i] * 4;
            cp_async16z(sb + sdstB[i], gb, rg < N);
        }
    };

    issue_tile(0, 0);
    cp_commit();
    if (ntiles > 1) issue_tile(1, 1);
    cp_commit();

    int lr8 = lane & 7;
    uint32_t a_rowb[4], b_rowb[4];
#pragma unroll
    for (int mt = 0; mt < 4; mt++) {
        int ar = warp_m * 64 + mt * 16 + ((lane & 8) ? 8 : 0) + lr8;
        a_rowb[mt] = (uint32_t)(ar * 128);
    }
#pragma unroll
    for (int nt = 0; nt < 4; nt++) {
        int br = warp_n * 32 + nt * 8 + lr8;
        b_rowb[nt] = (uint32_t)(br * 128 + STAGE_FLOATS * 4);
    }
    uint32_t a_csel = (lane & 16) ? 1u : 0u;
    uint32_t b_csel = (lane & 8) ? 1u : 0u;
    uint32_t swmask = (uint32_t)lr8;

    for (int kt = 0; kt < ntiles; kt++) {
        cp_wait1();
        __syncthreads();

        int tn = kt + 2;
        if (tn < ntiles) issue_tile(tn, tn % 3);
        cp_commit();

        uint32_t sb = smem_base + (uint32_t)((kt % 3) * 2 * STAGE_FLOATS * 4);

#pragma unroll
        for (int ks = 0; ks < 4; ks++) {
            uint32_t af[4][4];
#pragma unroll
            for (int mt = 0; mt < 4; mt++) {
                uint32_t ch = ((uint32_t)(ks * 2) + a_csel) ^ swmask;
                ldsm_x4(af[mt][0], af[mt][1], af[mt][2], af[mt][3],
                        sb + a_rowb[mt] + ch * 16);
            }
            uint32_t bf[4][2];
#pragma unroll
            for (int nt = 0; nt < 4; nt++) {
                uint32_t ch = ((uint32_t)(ks * 2) + b_csel) ^ swmask;
                ldsm_x2(bf[nt][0], bf[nt][1], sb + b_rowb[nt] + ch * 16);
            }
#pragma unroll
            for (int mt = 0; mt < 4; mt++)
#pragma unroll
                for (int nt = 0; nt < 4; nt++)
                    mma_tf32(acc[mt][nt][0], acc[mt][nt][1], acc[mt][nt][2], acc[mt][nt][3],
                             af[mt][0], af[mt][1], af[mt][2], af[mt][3],
                             bf[nt][0], bf[nt][1]);
        }
    }

#pragma unroll
    for (int mt = 0; mt < 4; mt++) {
        int row = block_row + warp_m * 64 + mt * 16 + gid;
#pragma unroll
        for (int nt = 0; nt < 4; nt++) {
            int col0 = block_col + warp_n * 32 + nt * 8 + 2 * tig;
            if (col0 < N) {
                float2 v0, v1;
                v0.x = apply_epi(acc[mt][nt][0], mode, bias, col0);
                v0.y = apply_epi(acc[mt][nt][1], mode, bias, col0 + 1);
                v1.x = apply_epi(acc[mt][nt][2], mode, bias, col0);
                v1.y = apply_epi(acc[mt][nt][3], mode, bias, col0 + 1);
                if (rnd) {
                    v0.x = tf32f(v0.x); v0.y = tf32f(v0.y);
                    v1.x = tf32f(v1.x); v1.y = tf32f(v1.y);
                }
                *(float2*)(C + (size_t)row * N + col0) = v0;
                *(float2*)(C + (size_t)(row + 8) * N + col0) = v1;
            }
        }
    }
}

// ---------------- prep kernel ----------------
__global__ void prep_kernel(float* __restrict__ Kb, float* __restrict__ Vb,
                            const float* __restrict__ Ab, const float* __restrict__ VMIXb,
                            const float* __restrict__ vfirst,
                            const float* __restrict__ k_k, const float* __restrict__ k_a,
                            float* __restrict__ AKK, float* __restrict__ BKK) {
    int bt = blockIdx.x;
    int lane = threadIdx.x & 31;
    int h = threadIdx.x >> 5;
    int d0 = h * HD_ + lane, d1 = d0 + 32;
    size_t i0 = (size_t)bt * D_ + d0;
    size_t i1 = i0 + 32;

    float k0 = Kb[i0], k1 = Kb[i1];
    float kk0 = k0 * __ldg(&k_k[d0]);
    float kk1 = k1 * __ldg(&k_k[d1]);
    float ss = kk0 * kk0 + kk1 * kk1;
#pragma unroll
    for (int o = 16; o > 0; o >>= 1) ss += __shfl_xor_sync(0xffffffffu, ss, o);
    float inv = 1.0f / fmaxf(sqrtf(ss), 1e-12f);
    kk0 *= inv; kk1 *= inv;

    float a0v = Ab[i0], a1v = Ab[i1];
    AKK[i0] = -kk0;        AKK[i1] = -kk1;
    BKK[i0] = kk0 * a0v;   BKK[i1] = kk1 * a1v;

    Kb[i0] = k0 * (1.0f + (a0v - 1.0f) * __ldg(&k_a[d0]));
    Kb[i1] = k1 * (1.0f + (a1v - 1.0f) * __ldg(&k_a[d1]));

    float v0v = Vb[i0], v1v = Vb[i1];
    Vb[i0] = v0v + (vfirst[i0] - v0v) * VMIXb[i0];
    Vb[i1] = v1v + (vfirst[i1] - v1v) * VMIXb[i1];
}

// ---------------- scan kernel v9: 8 warps per (b,h), k-split x4, no barriers ----------------
// SC points at R; arrays at SC + arr*BTD: R(0) EW(1) K(2) V(3) AKK(4) BKK(5)
// grid = 1024 blocks of 32 threads; block = (bh, eighth of 8 V-rows).
// lane = row_local*4 + kq: row = eighth*8 + (lane>>2), k-quarter = lane&3 (16 cols), S[16].
__global__ __launch_bounds__(32)
void scan_kernel(const float* __restrict__ SC, float* __restrict__ O) {
    int bh = blockIdx.x >> 3;
    int eig = blockIdx.x & 7;
    int b = bh >> 4;
    int h = bh & 15;
    int lane = threadIdx.x;           // 0..31
    int i = eig * 8 + (lane >> 2);    // V row 0..63
    int cb = (lane & 3) * 16;         // k-col base

    __shared__ __align__(16) float ring[8][6][64];   // 12 KB

    float S[16];
#pragma unroll
    for (int k = 0; k < 16; k++) S[k] = 0.0f;

    size_t base = (size_t)b * T_ * D_ + (size_t)h * HD_;
    const unsigned FULL = 0xffffffffu;
    uint32_t rb = smem_u32(ring);

    // loader: 96 16B-chunks per step over 32 lanes (3 each)
    auto load_step = [&](int t, int slot) {
#pragma unroll
        for (int j = 0; j < 3; j++) {
            int ch = lane + j * 32;
            int a_ = ch >> 4;
            int e_ = (ch & 15) << 2;
            const float* g = SC + (size_t)a_ * BTD + base + (size_t)t * D_ + e_;
            cp_async16(rb + (uint32_t)(((slot * 6 + a_) * 64 + e_) * 4), g);
        }
    };

    // prologue: stages 0..6 (7 groups outstanding)
#pragma unroll
    for (int t = 0; t < 7; t++) {
        load_step(t, t);
        cp_commit();
    }

    for (int t = 0; t < T_; t++) {
        cp_wait6();
        __syncwarp();

        int tn = t + 7;
        if (tn < T_) load_step(tn, tn & 7);
        cp_commit();

        int s = t & 7;
        const float* vr = &ring[s][0][0];
        const float* vw = &ring[s][1][0];
        const float* vk = &ring[s][2][0];
        const float* vv = &ring[s][3][0];
        const float* va = &ring[s][4][0];
        const float* vb = &ring[s][5][0];

        float vi = vv[i];

        // sa partial over this thread's 16 k-cols
        float sa0 = 0.f, sa1 = 0.f, sa2 = 0.f, sa3 = 0.f;
#pragma unroll
        for (int q = 0; q < 4; q++) {
            float4 a4 = *(const float4*)(va + cb + q * 4);
            sa0 = fmaf(S[q * 4 + 0], a4.x, sa0);
            sa1 = fmaf(S[q * 4 + 1], a4.y, sa1);
            sa2 = fmaf(S[q * 4 + 2], a4.z, sa2);
            sa3 = fmaf(S[q * 4 + 3], a4.w, sa3);
        }
        float sa = (sa0 + sa1) + (sa2 + sa3);
        sa += __shfl_xor_sync(FULL, sa, 1);
        sa += __shfl_xor_sync(FULL, sa, 2);

        float o0 = 0.f, o1 = 0.f, o2 = 0.f, o3 = 0.f;
#pragma unroll
        for (int q = 0; q < 4; q++) {
            float4 w4 = *(const float4*)(vw + cb + q * 4);
            float4 k4 = *(const float4*)(vk + cb + q * 4);
            float4 b4 = *(const float4*)(vb + cb + q * 4);
            float4 r4 = *(const float4*)(vr + cb + q * 4);
            S[q * 4 + 0] = fmaf(S[q * 4 + 0], w4.x, fmaf(sa, b4.x, vi * k4.x));
            S[q * 4 + 1] = fmaf(S[q * 4 + 1], w4.y, fmaf(sa, b4.y, vi * k4.y));
            S[q * 4 + 2] = fmaf(S[q * 4 + 2], w4.z, fmaf(sa, b4.z, vi * k4.z));
            S[q * 4 + 3] = fmaf(S[q * 4 + 3], w4.w, fmaf(sa, b4.w, vi * k4.w));
            o0 = fmaf(S[q * 4 + 0], r4.x, o0);
            o1 = fmaf(S[q * 4 + 1], r4.y, o1);
            o2 = fmaf(S[q * 4 + 2], r4.z, o2);
            o3 = fmaf(S[q * 4 + 3], r4.w, o3);
        }
        float op = (o0 + o1) + (o2 + o3);
        op += __shfl_xor_sync(FULL, op, 1);
        op += __shfl_xor_sync(FULL, op, 2);
        if ((lane & 3) == 0) O[base + (size_t)t * D_ + i] = op;
    }
}

// ---------------- post kernel: groupnorm + bonus + gate (tf32-rounded out) ----------------
__global__ void post_kernel(const float* __restrict__ O, const float* __restrict__ R,
                            const float* __restrict__ Kb, const float* __restrict__ Vb,
                            const float* __restrict__ G, const float* __restrict__ r_k,
                            const float* __restrict__ gn_w, const float* __restrict__ gn_b,
                            float* __restrict__ GATED) {
    int bt = blockIdx.x;
    int lane = threadIdx.x & 31;
    int h = threadIdx.x >> 5;
    int d0 = h * HD_ + lane, d1 = d0 + 32;
    size_t i0 = (size_t)bt * D_ + d0;
    size_t i1 = i0 + 32;

    float o0 = O[i0], o1 = O[i1];
    float s = o0 + o1;
    float sq = o0 * o0 + o1 * o1;
    float dot = R[i0] * Kb[i0] * __ldg(&r_k[d0]) + R[i1] * Kb[i1] * __ldg(&r_k[d1]);
#pragma unroll
    for (int o = 16; o > 0; o >>= 1) {
        s   += __shfl_xor_sync(0xffffffffu, s, o);
        sq  += __shfl_xor_sync(0xffffffffu, sq, o);
        dot += __shfl_xor_sync(0xffffffffu, dot, o);
    }
    float mean = s * (1.0f / 64.0f);
    float var = sq * (1.0f / 64.0f) - mean * mean;
    float rstd = rsqrtf(var + GN_EPS);
    float on0 = (o0 - mean) * rstd * __ldg(&gn_w[d0]) + __ldg(&gn_b[d0]);
    float on1 = (o1 - mean) * rstd * __ldg(&gn_w[d1]) + __ldg(&gn_b[d1]);
    on0 += dot * Vb[i0];
    on1 += dot * Vb[i1];
    GATED[i0] = tf32f(on0 * G[i0]);
    GATED[i1] = tf32f(on1 * G[i1]);
}

// ---------------- host launchers ----------------
static void run_tgemm(const float* A, const float* Bt, float* C,
                      int M, int N, int K, int mode, const float* bias, int rnd) {
    dim3 grid((N + 127) / 128, M / 128);
    tgemm_kernel<<<grid, 256, GEMM_SMEM>>>(A, Bt, C, M, N, K, mode, bias, rnd);
}
static void run_transpose(const float* in, float* out, int K, int N) {
    dim3 grid((N + 31) / 32, (K + 31) / 32);
    transpose_kernel<<<grid, dim3(32, 8)>>>(in, out, K, N);
}

extern "C" void kernel_launch(void* const* d_in, const int* in_sizes, int n_in,
                              void* d_out, int out_size) {
    const float* x       = (const float*)d_in[0];
    const float* v_first = (const float*)d_in[1];
    const float* x_x     = (const float*)d_in[2];
    const float* W_r     = (const float*)d_in[3];
    const float* W_k     = (const float*)d_in[4];
    const float* W_v     = (const float*)d_in[5];
    const float* W_o     = (const float*)d_in[6];
    const float* w1      = (const float*)d_in[7];
    const float* w2      = (const float*)d_in[8];
    const float* w0      = (const float*)d_in[9];
    const float* a1      = (const float*)d_in[10];
    const float* a2      = (const float*)d_in[11];
    const float* a0      = (const float*)d_in[12];
    const float* v1      = (const float*)d_in[13];
    const float* v2      = (const float*)d_in[14];
    const float* v0      = (const float*)d_in[15];
    const float* g1      = (const float*)d_in[16];
    const float* g2      = (const float*)d_in[17];
    const float* k_k     = (const float*)d_in[18];
    const float* k_a     = (const float*)d_in[19];
    const float* r_k     = (const float*)d_in[20];
    const float* gn_w    = (const float*)d_in[21];
    const float* gn_b    = (const float*)d_in[22];
    float* out = (float*)d_out;

    static bool attr_done = false;
    if (!attr_done) {
        cudaFuncSetAttribute(tgemm_kernel,
                             cudaFuncAttributeMaxDynamicSharedMemorySize, GEMM_SMEM);
        attr_done = true;
    }

    float* sc;
    cudaGetSymbolAddress((void**)&sc, g_scratch);

    float* XR    = sc + 0 * BTD;
    float* XW    = sc + 1 * BTD;
    float* XK    = sc + 2 * BTD;
    float* XV    = sc + 3 * BTD;
    float* XA    = sc + 4 * BTD;
    float* XG    = sc + 5 * BTD;
    float* Rb    = sc + 6 * BTD;
    float* EWb   = sc + 7 * BTD;
    float* Kb    = sc + 8 * BTD;
    float* Vb    = sc + 9 * BTD;
    float* AKKb  = sc + 10 * BTD;
    float* BKKb  = sc + 11 * BTD;
    float* Ab    = sc + 12 * BTD;
    float* VMIXb = sc + 13 * BTD;
    float* Ob    = sc + 14 * BTD;
    float* Gb    = sc + 15 * BTD;
    float* GATED = sc + 16 * BTD;
    float* T1b   = sc + T1_OFF;
    float* T2b   = sc + T2_OFF;
    float* T3b   = sc + T3_OFF;
    float* T4b   = sc + T4_OFF;
    float* WRT   = sc + WRT_OFF;
    float* WKT   = sc + WKT_OFF;
    float* WVT   = sc + WVT_OFF;
    float* WOT   = sc + WOT_OFF;
    float* W1T   = sc + W1T_OFF;
    float* W2T   = sc + W2T_OFF;
    float* A1T   = sc + A1T_OFF;
    float* A2T   = sc + A2T_OFF;
    float* V1T   = sc + V1T_OFF;
    float* V2T   = sc + V2T_OFF;
    float* G1T   = sc + G1T_OFF;
    float* G2T   = sc + G2T_OFF;

    mix_kernel<<<(unsigned)((BTD / 4 + 255) / 256), 256>>>(
        (const float4*)x, (const float4*)x_x, (float4*)XR);
    run_transpose(W_r, WRT, D_, D_);
    run_transpose(W_k, WKT, D_, D_);
    run_tgemm(XR, WRT, Rb, (int)BT, D_, D_, 0, nullptr, 0);
    run_tgemm(XK, WKT, Kb, (int)BT, D_, D_, 0, nullptr, 0);
    run_transpose(W_v, WVT, D_, D_);
    run_tgemm(XV, WVT, Vb, (int)BT, D_, D_, 0, nullptr, 0);

    run_transpose(W_o, WOT, D_, D_);
    run_transpose(w1, W1T, D_, 64);
    run_transpose(w2, W2T, 64, D_);
    run_transpose(a1, A1T, D_, 64);
    run_transpose(a2, A2T, 64, D_);
    run_transpose(v1, V1T, D_, 32);
    run_transpose(v2, V2T, 32, D_);
    run_transpose(g1, G1T, D_, 160);
    run_transpose(g2, G2T, 160, D_);

    // low-rank chains
    run_tgemm(XW, W1T, T1b, (int)BT, 64, D_, 1, nullptr, 1);
    run_tgemm(T1b, W2T, EWb, (int)BT, D_, 64, 2, w0, 0);
    run_tgemm(XA, A1T, T2b, (int)BT, 64, D_, 0, nullptr, 1);
    run_tgemm(T2b, A2T, Ab, (int)BT, D_, 64, 3, a0, 0);
    run_tgemm(XV, V1T, T3b, (int)BT, 32, D_, 0, nullptr, 1);
    run_tgemm(T3b, V2T, VMIXb, (int)BT, D_, 32, 3, v0, 0);
    run_tgemm(XG, G1T, T4b, (int)BT, 160, D_, 4, nullptr, 1);
    run_tgemm(T4b, G2T, Gb, (int)BT, D_, 160, 0, nullptr, 0);

    // prep
    prep_kernel<<<(unsigned)BT, 512>>>(Kb, Vb, Ab, VMIXb, v_first, k_k, k_a, AKKb, BKKb);

    // sequential scan (8 warps per (b,h), warp-autonomous, k-split x4)
    scan_kernel<<<8 * B_ * H_, 32>>>(Rb, Ob);

    // groupnorm + bonus + gate
    post_kernel<<<(unsigned)BT, 512>>>(Ob, Rb, Kb, Vb, Gb, r_k, gn_w, gn_b, GATED);

    // output projection
    run_tgemm(GATED, WOT, out, (int)BT, D_, D_, 0, nullptr, 0);

    // v_first passthrough
    if ((size_t)out_size >= 2 * BTD) {
        cudaMemcpyAsync(out + BTD, v_first, BTD * sizeof(float),
                        cudaMemcpyDeviceToDevice, 0);
    }
}

// round 15
// speedup vs baseline: 1.2927x; 1.2927x over previous
#include <cuda_runtime.h>
#include <math.h>
#include <stdint.h>

// ---------------- problem constants ----------------
constexpr int   B_  = 8;
constexpr int   T_  = 2048;
constexpr int   D_  = 1024;
constexpr int   H_  = 16;
constexpr int   HD_ = 64;
constexpr size_t BTD = (size_t)B_ * T_ * D_;   // 16,777,216
constexpr size_t BT  = (size_t)B_ * T_;        // 16,384
constexpr float LOG_W_SCALE = -0.6065306597126334f;
constexpr float GN_EPS = (float)HD_ * 1e-5f;

// ---------------- scratch pool ----------------
constexpr size_t N_SLOTS = 17;
constexpr size_t T1_OFF = N_SLOTS * BTD;
constexpr size_t T2_OFF = T1_OFF + BT * 64;
constexpr size_t T3_OFF = T2_OFF + BT * 64;
constexpr size_t T4_OFF = T3_OFF + BT * 32;
constexpr size_t WT_OFF  = T4_OFF + BT * 160;
constexpr size_t WRT_OFF = WT_OFF;
constexpr size_t WKT_OFF = WRT_OFF + (size_t)D_ * D_;
constexpr size_t WVT_OFF = WKT_OFF + (size_t)D_ * D_;
constexpr size_t WOT_OFF = WVT_OFF + (size_t)D_ * D_;
constexpr size_t W1T_OFF = WOT_OFF + (size_t)D_ * D_;
constexpr size_t W2T_OFF = W1T_OFF + (size_t)64 * 1024;
constexpr size_t A1T_OFF = W2T_OFF + (size_t)64 * 1024;
constexpr size_t A2T_OFF = A1T_OFF + (size_t)64 * 1024;
constexpr size_t V1T_OFF = A2T_OFF + (size_t)64 * 1024;
constexpr size_t V2T_OFF = V1T_OFF + (size_t)32 * 1024;
constexpr size_t G1T_OFF = V2T_OFF + (size_t)32 * 1024;
constexpr size_t G2T_OFF = G1T_OFF + (size_t)160 * 1024;
constexpr size_t SCRATCH_FLOATS = G2T_OFF + (size_t)160 * 1024;

__device__ float g_scratch[SCRATCH_FLOATS];

// ---------------- helpers ----------------
__device__ __forceinline__ uint32_t tf32bits(float x) {
    uint32_t y;
    asm("cvt.rna.tf32.f32 %0, %1;" : "=r"(y) : "f"(x));
    return y;
}
__device__ __forceinline__ float tf32f(float x) {
    return __uint_as_float(tf32bits(x));
}
__device__ __forceinline__ void mma_tf32(float& c0, float& c1, float& c2, float& c3,
                                         uint32_t a0, uint32_t a1, uint32_t a2, uint32_t a3,
                                         uint32_t b0, uint32_t b1) {
    asm volatile(
        "mma.sync.aligned.m16n8k8.row.col.f32.tf32.tf32.f32 "
        "{%0,%1,%2,%3}, {%4,%5,%6,%7}, {%8,%9}, {%0,%1,%2,%3};"
        : "+f"(c0), "+f"(c1), "+f"(c2), "+f"(c3)
        : "r"(a0), "r"(a1), "r"(a2), "r"(a3), "r"(b0), "r"(b1));
}
__device__ __forceinline__ void ldsm_x4(uint32_t& r0, uint32_t& r1, uint32_t& r2,
                                        uint32_t& r3, uint32_t addr) {
    asm volatile("ldmatrix.sync.aligned.m8n8.x4.shared.b16 {%0,%1,%2,%3}, [%4];"
                 : "=r"(r0), "=r"(r1), "=r"(r2), "=r"(r3) : "r"(addr));
}
__device__ __forceinline__ void ldsm_x2(uint32_t& r0, uint32_t& r1, uint32_t addr) {
    asm volatile("ldmatrix.sync.aligned.m8n8.x2.shared.b16 {%0,%1}, [%2];"
                 : "=r"(r0), "=r"(r1) : "r"(addr));
}
__device__ __forceinline__ uint32_t smem_u32(const void* p) {
    uint32_t a;
    asm("{ .reg .u64 t; cvta.to.shared.u64 t, %1; cvt.u32.u64 %0, t; }"
        : "=r"(a) : "l"(p));
    return a;
}
__device__ __forceinline__ void cp_async16(uint32_t saddr, const void* gptr) {
    asm volatile("cp.async.cg.shared.global [%0], [%1], 16;"
                 :: "r"(saddr), "l"(gptr) : "memory");
}
__device__ __forceinline__ void cp_async16z(uint32_t saddr, const void* gptr, int valid) {
    asm volatile("cp.async.cg.shared.global [%0], [%1], 16, %2;"
                 :: "r"(saddr), "l"(gptr), "r"(valid ? 16 : 0) : "memory");
}
__device__ __forceinline__ void cp_commit() {
    asm volatile("cp.async.commit_group;" ::: "memory");
}
__device__ __forceinline__ void cp_wait1() {
    asm volatile("cp.async.wait_group 1;" ::: "memory");
}
__device__ __forceinline__ void cp_wait2() {
    asm volatile("cp.async.wait_group 2;" ::: "memory");
}
__device__ __forceinline__ float apply_epi(float f, int mode,
                                           const float* __restrict__ bias, int colg) {
    if (mode == 1) {
        f = tanhf(f);
    } else if (mode == 2) {
        float s = 1.0f / (1.0f + expf(-(__ldg(&bias[colg]) + f)));
        f = expf(LOG_W_SCALE * s);
    } else if (mode == 3) {
        f = 1.0f / (1.0f + expf(-(__ldg(&bias[colg]) + f)));
    } else if (mode == 4) {
        f = 1.0f / (1.0f + expf(-f));
    }
    return f;
}

// ---------------- kernel: token-shift mixes, float4, tf32-rounded ----------------
__global__ void mix_kernel(const float4* __restrict__ x4,
                           const float4* __restrict__ xx4,
                           float4* __restrict__ out /* 6 x BTD/4 */) {
    size_t idx4 = (size_t)blockIdx.x * blockDim.x + threadIdx.x;
    if (idx4 >= BTD / 4) return;
    int d4 = (int)(idx4 & (D_ / 4 - 1));
    int t = (int)((idx4 >> 8) & (T_ - 1));
    float4 xc = x4[idx4];
    float4 xp = make_float4(0.f, 0.f, 0.f, 0.f);
    if (t > 0) xp = x4[idx4 - D_ / 4];
    float dx = xp.x - xc.x, dy = xp.y - xc.y, dz = xp.z - xc.z, dw = xp.w - xc.w;
#pragma unroll
    for (int j = 0; j < 6; j++) {
        float4 cf = __ldg(&xx4[j * (D_ / 4) + d4]);
        float4 r;
        r.x = tf32f(xc.x + dx * cf.x);
        r.y = tf32f(xc.y + dy * cf.y);
        r.z = tf32f(xc.z + dz * cf.z);
        r.w = tf32f(xc.w + dw * cf.w);
        out[(size_t)j * (BTD / 4) + idx4] = r;
    }
}

// ---------------- transpose kernel: in[K,N] -> out[N,K], tf32-rounded ----------------
__global__ void transpose_kernel(const float* __restrict__ in, float* __restrict__ out,
                                 int K, int N) {
    __shared__ float tile[32][33];
    int n0 = blockIdx.x * 32, k0 = blockIdx.y * 32;
    int tx = threadIdx.x, ty = threadIdx.y;  // 32 x 8
#pragma unroll
    for (int i = 0; i < 32; i += 8) {
        int k = k0 + ty + i, n = n0 + tx;
        if (k < K && n < N) tile[ty + i][tx] = tf32f(in[(size_t)k * N + n]);
    }
    __syncthreads();
#pragma unroll
    for (int i = 0; i < 32; i += 8) {
        int n = n0 + ty + i, k = k0 + tx;
        if (n < N && k < K) out[(size_t)n * K + k] = tile[tx][ty + i];
    }
}

// ---------------- tf32 GEMM: 3-stage cp.async, swizzled smem, 1 barrier/tile ----------------
constexpr int STAGE_FLOATS = 128 * 32;
constexpr unsigned GEMM_SMEM = 3 * 2 * STAGE_FLOATS * 4;     // 98304 B
__global__ __launch_bounds__(256)
void tgemm_kernel(const float* __restrict__ A, const float* __restrict__ Bt,
                  float* __restrict__ C, int M, int N, int K,
                  int mode, const float* __restrict__ bias, int rnd) {
    extern __shared__ float dsm[];
    uint32_t smem_base = smem_u32(dsm);

    int tid = threadIdx.x;
    int wid = tid >> 5, lane = tid & 31;
    int warp_m = wid >> 2;
    int warp_n = wid & 3;
    int gid = lane >> 2;
    int tig = lane & 3;
    int block_row = blockIdx.y * 128;
    int block_col = blockIdx.x * 128;

    float acc[4][4][4];
#pragma unroll
    for (int mt = 0; mt < 4; mt++)
#pragma unroll
        for (int nt = 0; nt < 4; nt++)
#pragma unroll
            for (int q = 0; q < 4; q++) acc[mt][nt][q] = 0.0f;

    int lr[4], lcc[4];
    uint32_t sdstA[4], sdstB[4];
#pragma unroll
    for (int i = 0; i < 4; i++) {
        int f4 = tid + i * 256;
        lr[i] = f4 >> 3;
        lcc[i] = f4 & 7;
        uint32_t sw = (uint32_t)(lcc[i] ^ (lr[i] & 7));
        sdstA[i] = (uint32_t)(lr[i] * 128 + sw * 16);
        sdstB[i] = sdstA[i] + STAGE_FLOATS * 4;
    }

    int ntiles = K >> 5;

    auto issue_tile = [&](int kt, int stage) {
        uint32_t sb = smem_base + (uint32_t)(stage * 2 * STAGE_FLOATS * 4);
        int k0 = kt << 5;
#pragma unroll
        for (int i = 0; i < 4; i++) {
            const float* ga = A + (size_t)(block_row + lr[i]) * K + k0 + lcc[i] * 4;
            cp_async16(sb + sdstA[i], ga);
            int rg = block_col + lr[i];
            const float* gb = Bt + (size_t)(rg < N ? rg : 0) * K + k0 + lcc[i] * 4;
            cp_async16z(sb + sdstB[i], gb, rg < N);
        }
    };

    issue_tile(0, 0);
    cp_commit();
    if (ntiles > 1) issue_tile(1, 1);
    cp_commit();

    int lr8 = lane & 7;
    uint32_t a_rowb[4], b_rowb[4];
#pragma unroll
    for (int mt = 0; mt < 4; mt++) {
        int ar = warp_m * 64 + mt * 16 + ((lane & 8) ? 8 : 0) + lr8;
        a_rowb[mt] = (uint32_t)(ar * 128);
    }
#pragma unroll
    for (int nt = 0; nt < 4; nt++) {
        int br = warp_n * 32 + nt * 8 + lr8;
        b_rowb[nt] = (uint32_t)(br * 128 + STAGE_FLOATS * 4);
    }
    uint32_t a_csel = (lane & 16) ? 1u : 0u;
    uint32_t b_csel = (lane & 8) ? 1u : 0u;
    uint32_t swmask = (uint32_t)lr8;

    for (int kt = 0; kt < ntiles; kt++) {
        cp_wait1();
        __syncthreads();

        int tn = kt + 2;
        if (tn < ntiles) issue_tile(tn, tn % 3);
        cp_commit();

        uint32_t sb = smem_base + (uint32_t)((kt % 3) * 2 * STAGE_FLOATS * 4);

#pragma unroll
        for (int ks = 0; ks < 4; ks++) {
            uint32_t af[4][4];
#pragma unroll
            for (int mt = 0; mt < 4; mt++) {
                uint32_t ch = ((uint32_t)(ks * 2) + a_csel) ^ swmask;
                ldsm_x4(af[mt][0], af[mt][1], af[mt][2], af[mt][3],
                        sb + a_rowb[mt] + ch * 16);
            }
            uint32_t bf[4][2];
#pragma unroll
            for (int nt = 0; nt < 4; nt++) {
                uint32_t ch = ((uint32_t)(ks * 2) + b_csel) ^ swmask;
                ldsm_x2(bf[nt][0], bf[nt][1], sb + b_rowb[nt] + ch * 16);
            }
#pragma unroll
            for (int mt = 0; mt < 4; mt++)
#pragma unroll
                for (int nt = 0; nt < 4; nt++)
                    mma_tf32(acc[mt][nt][0], acc[mt][nt][1], acc[mt][nt][2], acc[mt][nt][3],
                             af[mt][0], af[mt][1], af[mt][2], af[mt][3],
                             bf[nt][0], bf[nt][1]);
        }
    }

#pragma unroll
    for (int mt = 0; mt < 4; mt++) {
        int row = block_row + warp_m * 64 + mt * 16 + gid;
#pragma unroll
        for (int nt = 0; nt < 4; nt++) {
            int col0 = block_col + warp_n * 32 + nt * 8 + 2 * tig;
            if (col0 < N) {
                float2 v0, v1;
                v0.x = apply_epi(acc[mt][nt][0], mode, bias, col0);
                v0.y = apply_epi(acc[mt][nt][1], mode, bias, col0 + 1);
                v1.x = apply_epi(acc[mt][nt][2], mode, bias, col0);
                v1.y = apply_epi(acc[mt][nt][3], mode, bias, col0 + 1);
                if (rnd) {
                    v0.x = tf32f(v0.x); v0.y = tf32f(v0.y);
                    v1.x = tf32f(v1.x); v1.y = tf32f(v1.y);
                }
                *(float2*)(C + (size_t)row * N + col0) = v0;
                *(float2*)(C + (size_t)(row + 8) * N + col0) = v1;
            }
        }
    }
}

// ---------------- prep kernel ----------------
__global__ void prep_kernel(float* __restrict__ Kb, float* __restrict__ Vb,
                            const float* __restrict__ Ab, const float* __restrict__ VMIXb,
                            const float* __restrict__ vfirst,
                            const float* __restrict__ k_k, const float* __restrict__ k_a,
                            float* __restrict__ AKK, float* __restrict__ BKK) {
    int bt = blockIdx.x;
    int lane = threadIdx.x & 31;
    int h = threadIdx.x >> 5;
    int d0 = h * HD_ + lane, d1 = d0 + 32;
    size_t i0 = (size_t)bt * D_ + d0;
    size_t i1 = i0 + 32;

    float k0 = Kb[i0], k1 = Kb[i1];
    float kk0 = k0 * __ldg(&k_k[d0]);
    float kk1 = k1 * __ldg(&k_k[d1]);
    float ss = kk0 * kk0 + kk1 * kk1;
#pragma unroll
    for (int o = 16; o > 0; o >>= 1) ss += __shfl_xor_sync(0xffffffffu, ss, o);
    float inv = 1.0f / fmaxf(sqrtf(ss), 1e-12f);
    kk0 *= inv; kk1 *= inv;

    float a0v = Ab[i0], a1v = Ab[i1];
    AKK[i0] = -kk0;        AKK[i1] = -kk1;
    BKK[i0] = kk0 * a0v;   BKK[i1] = kk1 * a1v;

    Kb[i0] = k0 * (1.0f + (a0v - 1.0f) * __ldg(&k_a[d0]));
    Kb[i1] = k1 * (1.0f + (a1v - 1.0f) * __ldg(&k_a[d1]));

    float v0v = Vb[i0], v1v = Vb[i1];
    Vb[i0] = v0v + (vfirst[i0] - v0v) * VMIXb[i0];
    Vb[i1] = v1v + (vfirst[i1] - v1v) * VMIXb[i1];
}

// ---------------- scan kernel v10: R13 layout + 2-step pairs, 1 wait/sync per pair ----------------
// SC points at R; arrays at SC + arr*BTD: R(0) EW(1) K(2) V(3) AKK(4) BKK(5)
// grid = 512 blocks of 32 threads; block = (bh, quarter of 16 V-rows).
// lane: row = quar*16 + (lane>>1), k-half = lane&1 (32 k-cols), S[32] regs.
__global__ __launch_bounds__(32)
void scan_kernel(const float* __restrict__ SC, float* __restrict__ O) {
    int bh = blockIdx.x >> 2;
    int quar = blockIdx.x & 3;
    int b = bh >> 4;
    int h = bh & 15;
    int lane = threadIdx.x;           // 0..31
    int i = quar * 16 + (lane >> 1);  // V row 0..63
    int cb = (lane & 1) * 32;         // k-col base

    __shared__ __align__(16) float ring[8][6][64];   // 12 KB

    float S[32];
#pragma unroll
    for (int k = 0; k < 32; k++) S[k] = 0.0f;

    size_t base = (size_t)b * T_ * D_ + (size_t)h * HD_;
    const unsigned FULL = 0xffffffffu;
    uint32_t rb = smem_u32(ring);

    // loader: 96 16B-chunks per step over 32 lanes (3 each)
    auto load_step = [&](int t, int slot) {
#pragma unroll
        for (int j = 0; j < 3; j++) {
            int ch = lane + j * 32;
            int a_ = ch >> 4;
            int e_ = (ch & 15) << 2;
            const float* g = SC + (size_t)a_ * BTD + base + (size_t)t * D_ + e_;
            cp_async16(rb + (uint32_t)(((slot * 6 + a_) * 64 + e_) * 4), g);
        }
    };

    // one scan step on ring slot s (thread-local except two 1-hop shfls)
    auto do_step = [&](int t, int s) {
        const float* vr = &ring[s][0][0];
        const float* vw = &ring[s][1][0];
        const float* vk = &ring[s][2][0];
        const float* vv = &ring[s][3][0];
        const float* va = &ring[s][4][0];
        const float* vb = &ring[s][5][0];

        float vi = vv[i];

        float sa0 = 0.f, sa1 = 0.f, sa2 = 0.f, sa3 = 0.f;
#pragma unroll
        for (int q = 0; q < 8; q++) {
            float4 a4 = *(const float4*)(va + cb + q * 4);
            sa0 = fmaf(S[q * 4 + 0], a4.x, sa0);
            sa1 = fmaf(S[q * 4 + 1], a4.y, sa1);
            sa2 = fmaf(S[q * 4 + 2], a4.z, sa2);
            sa3 = fmaf(S[q * 4 + 3], a4.w, sa3);
        }
        float sa = (sa0 + sa1) + (sa2 + sa3);
        sa += __shfl_xor_sync(FULL, sa, 1);

        float o0 = 0.f, o1 = 0.f, o2 = 0.f, o3 = 0.f;
#pragma unroll
        for (int q = 0; q < 8; q++) {
            float4 w4 = *(const float4*)(vw + cb + q * 4);
            float4 k4 = *(const float4*)(vk + cb + q * 4);
            float4 b4 = *(const float4*)(vb + cb + q * 4);
            float4 r4 = *(const float4*)(vr + cb + q * 4);
            S[q * 4 + 0] = fmaf(S[q * 4 + 0], w4.x, fmaf(sa, b4.x, vi * k4.x));
            S[q * 4 + 1] = fmaf(S[q * 4 + 1], w4.y, fmaf(sa, b4.y, vi * k4.y));
            S[q * 4 + 2] = fmaf(S[q * 4 + 2], w4.z, fmaf(sa, b4.z, vi * k4.z));
            S[q * 4 + 3] = fmaf(S[q * 4 + 3], w4.w, fmaf(sa, b4.w, vi * k4.w));
            o0 = fmaf(S[q * 4 + 0], r4.x, o0);
            o1 = fmaf(S[q * 4 + 1], r4.y, o1);
            o2 = fmaf(S[q * 4 + 2], r4.z, o2);
            o3 = fmaf(S[q * 4 + 3], r4.w, o3);
        }
        float op = (o0 + o1) + (o2 + o3);
        op += __shfl_xor_sync(FULL, op, 1);
        if ((lane & 1) == 0) O[base + (size_t)t * D_ + i] = op;
    };

    // prologue: pairs (0,1),(2,3),(4,5) -> 3 committed groups
#pragma unroll
    for (int p = 0; p < 3; p++) {
        load_step(2 * p, 2 * p);
        load_step(2 * p + 1, 2 * p + 1);
        cp_commit();
    }

    for (int t = 0; t < T_; t += 2) {
        cp_wait2();        // pair (t, t+1) landed
        __syncwarp();      // all lanes past pair (t-2, t-1) reads

        // refill pair (t+6, t+7) -> slots used by pair (t-2, t-1)
        int tn = t + 6;
        if (tn < T_) {
            load_step(tn, tn & 7);
            load_step(tn + 1, (tn + 1) & 7);
        }
        cp_commit();

        do_step(t, t & 7);
        do_step(t + 1, (t + 1) & 7);
    }
}

// ---------------- post kernel: groupnorm + bonus + gate (tf32-rounded out) ----------------
__global__ void post_kernel(const float* __restrict__ O, const float* __restrict__ R,
                            const float* __restrict__ Kb, const float* __restrict__ Vb,
                            const float* __restrict__ G, const float* __restrict__ r_k,
                            const float* __restrict__ gn_w, const float* __restrict__ gn_b,
                            float* __restrict__ GATED) {
    int bt = blockIdx.x;
    int lane = threadIdx.x & 31;
    int h = threadIdx.x >> 5;
    int d0 = h * HD_ + lane, d1 = d0 + 32;
    size_t i0 = (size_t)bt * D_ + d0;
    size_t i1 = i0 + 32;

    float o0 = O[i0], o1 = O[i1];
    float s = o0 + o1;
    float sq = o0 * o0 + o1 * o1;
    float dot = R[i0] * Kb[i0] * __ldg(&r_k[d0]) + R[i1] * Kb[i1] * __ldg(&r_k[d1]);
#pragma unroll
    for (int o = 16; o > 0; o >>= 1) {
        s   += __shfl_xor_sync(0xffffffffu, s, o);
        sq  += __shfl_xor_sync(0xffffffffu, sq, o);
        dot += __shfl_xor_sync(0xffffffffu, dot, o);
    }
    float mean = s * (1.0f / 64.0f);
    float var = sq * (1.0f / 64.0f) - mean * mean;
    float rstd = rsqrtf(var + GN_EPS);
    float on0 = (o0 - mean) * rstd * __ldg(&gn_w[d0]) + __ldg(&gn_b[d0]);
    float on1 = (o1 - mean) * rstd * __ldg(&gn_w[d1]) + __ldg(&gn_b[d1]);
    on0 += dot * Vb[i0];
    on1 += dot * Vb[i1];
    GATED[i0] = tf32f(on0 * G[i0]);
    GATED[i1] = tf32f(on1 * G[i1]);
}

// ---------------- host launchers ----------------
static void run_tgemm(const float* A, const float* Bt, float* C,
                      int M, int N, int K, int mode, const float* bias, int rnd) {
    dim3 grid((N + 127) / 128, M / 128);
    tgemm_kernel<<<grid, 256, GEMM_SMEM>>>(A, Bt, C, M, N, K, mode, bias, rnd);
}
static void run_transpose(const float* in, float* out, int K, int N) {
    dim3 grid((N + 31) / 32, (K + 31) / 32);
    transpose_kernel<<<grid, dim3(32, 8)>>>(in, out, K, N);
}

extern "C" void kernel_launch(void* const* d_in, const int* in_sizes, int n_in,
                              void* d_out, int out_size) {
    const float* x       = (const float*)d_in[0];
    const float* v_first = (const float*)d_in[1];
    const float* x_x     = (const float*)d_in[2];
    const float* W_r     = (const float*)d_in[3];
    const float* W_k     = (const float*)d_in[4];
    const float* W_v     = (const float*)d_in[5];
    const float* W_o     = (const float*)d_in[6];
    const float* w1      = (const float*)d_in[7];
    const float* w2      = (const float*)d_in[8];
    const float* w0      = (const float*)d_in[9];
    const float* a1      = (const float*)d_in[10];
    const float* a2      = (const float*)d_in[11];
    const float* a0      = (const float*)d_in[12];
    const float* v1      = (const float*)d_in[13];
    const float* v2      = (const float*)d_in[14];
    const float* v0      = (const float*)d_in[15];
    const float* g1      = (const float*)d_in[16];
    const float* g2      = (const float*)d_in[17];
    const float* k_k     = (const float*)d_in[18];
    const float* k_a     = (const float*)d_in[19];
    const float* r_k     = (const float*)d_in[20];
    const float* gn_w    = (const float*)d_in[21];
    const float* gn_b    = (const float*)d_in[22];
    float* out = (float*)d_out;

    static bool attr_done = false;
    if (!attr_done) {
        cudaFuncSetAttribute(tgemm_kernel,
                             cudaFuncAttributeMaxDynamicSharedMemorySize, GEMM_SMEM);
        attr_done = true;
    }

    float* sc;
    cudaGetSymbolAddress((void**)&sc, g_scratch);

    float* XR    = sc + 0 * BTD;
    float* XW    = sc + 1 * BTD;
    float* XK    = sc + 2 * BTD;
    float* XV    = sc + 3 * BTD;
    float* XA    = sc + 4 * BTD;
    float* XG    = sc + 5 * BTD;
    float* Rb    = sc + 6 * BTD;
    float* EWb   = sc + 7 * BTD;
    float* Kb    = sc + 8 * BTD;
    float* Vb    = sc + 9 * BTD;
    float* AKKb  = sc + 10 * BTD;
    float* BKKb  = sc + 11 * BTD;
    float* Ab    = sc + 12 * BTD;
    float* VMIXb = sc + 13 * BTD;
    float* Ob    = sc + 14 * BTD;
    float* Gb    = sc + 15 * BTD;
    float* GATED = sc + 16 * BTD;
    float* T1b   = sc + T1_OFF;
    float* T2b   = sc + T2_OFF;
    float* T3b   = sc + T3_OFF;
    float* T4b   = sc + T4_OFF;
    float* WRT   = sc + WRT_OFF;
    float* WKT   = sc + WKT_OFF;
    float* WVT   = sc + WVT_OFF;
    float* WOT   = sc + WOT_OFF;
    float* W1T   = sc + W1T_OFF;
    float* W2T   = sc + W2T_OFF;
    float* A1T   = sc + A1T_OFF;
    float* A2T   = sc + A2T_OFF;
    float* V1T   = sc + V1T_OFF;
    float* V2T   = sc + V2T_OFF;
    float* G1T   = sc + G1T_OFF;
    float* G2T   = sc + G2T_OFF;

    mix_kernel<<<(unsigned)((BTD / 4 + 255) / 256), 256>>>(
        (const float4*)x, (const float4*)x_x, (float4*)XR);
    run_transpose(W_r, WRT, D_, D_);
    run_transpose(W_k, WKT, D_, D_);
    run_tgemm(XR, WRT, Rb, (int)BT, D_, D_, 0, nullptr, 0);
    run_tgemm(XK, WKT, Kb, (int)BT, D_, D_, 0, nullptr, 0);
    run_transpose(W_v, WVT, D_, D_);
    run_tgemm(XV, WVT, Vb, (int)BT, D_, D_, 0, nullptr, 0);

    run_transpose(W_o, WOT, D_, D_);
    run_transpose(w1, W1T, D_, 64);
    run_transpose(w2, W2T, 64, D_);
    run_transpose(a1, A1T, D_, 64);
    run_transpose(a2, A2T, 64, D_);
    run_transpose(v1, V1T, D_, 32);
    run_transpose(v2, V2T, 32, D_);
    run_transpose(g1, G1T, D_, 160);
    run_transpose(g2, G2T, 160, D_);

    // low-rank chains
    run_tgemm(XW, W1T, T1b, (int)BT, 64, D_, 1, nullptr, 1);
    run_tgemm(T1b, W2T, EWb, (int)BT, D_, 64, 2, w0, 0);
    run_tgemm(XA, A1T, T2b, (int)BT, 64, D_, 0, nullptr, 1);
    run_tgemm(T2b, A2T, Ab, (int)BT, D_, 64, 3, a0, 0);
    run_tgemm(XV, V1T, T3b, (int)BT, 32, D_, 0, nullptr, 1);
    run_tgemm(T3b, V2T, VMIXb, (int)BT, D_, 32, 3, v0, 0);
    run_tgemm(XG, G1T, T4b, (int)BT, 160, D_, 4, nullptr, 1);
    run_tgemm(T4b, G2T, Gb, (int)BT, D_, 160, 0, nullptr, 0);

    // prep
    prep_kernel<<<(unsigned)BT, 512>>>(Kb, Vb, Ab, VMIXb, v_first, k_k, k_a, AKKb, BKKb);

    // sequential scan (4 warps per (b,h), warp-autonomous, k-split x2, 2-step pairs)
    scan_kernel<<<4 * B_ * H_, 32>>>(Rb, Ob);

    // groupnorm + bonus + gate
    post_kernel<<<(unsigned)BT, 512>>>(Ob, Rb, Kb, Vb, Gb, r_k, gn_w, gn_b, GATED);

    // output projection
    run_tgemm(GATED, WOT, out, (int)BT, D_, D_, 0, nullptr, 0);

    // v_first passthrough
    if ((size_t)out_size >= 2 * BTD) {
        cudaMemcpyAsync(out + BTD, v_first, BTD * sizeof(float),
                        cudaMemcpyDeviceToDevice, 0);
    }
}

// round 17
// speedup vs baseline: 1.3402x; 1.0367x over previous
#include <cuda_runtime.h>
#include <math.h>
#include <stdint.h>

// ---------------- problem constants ----------------
constexpr int   B_  = 8;
constexpr int   T_  = 2048;
constexpr int   D_  = 1024;
constexpr int   H_  = 16;
constexpr int   HD_ = 64;
constexpr size_t BTD = (size_t)B_ * T_ * D_;   // 16,777,216
constexpr size_t BT  = (size_t)B_ * T_;        // 16,384
constexpr float LOG_W_SCALE = -0.6065306597126334f;
constexpr float GN_EPS = (float)HD_ * 1e-5f;

// ---------------- scratch pool ----------------
constexpr size_t N_SLOTS = 17;
constexpr size_t T1_OFF = N_SLOTS * BTD;
constexpr size_t T2_OFF = T1_OFF + BT * 64;
constexpr size_t T3_OFF = T2_OFF + BT * 64;
constexpr size_t T4_OFF = T3_OFF + BT * 32;
constexpr size_t WT_OFF  = T4_OFF + BT * 160;
constexpr size_t WRT_OFF = WT_OFF;
constexpr size_t WKT_OFF = WRT_OFF + (size_t)D_ * D_;
constexpr size_t WVT_OFF = WKT_OFF + (size_t)D_ * D_;
constexpr size_t WOT_OFF = WVT_OFF + (size_t)D_ * D_;
constexpr size_t W1T_OFF = WOT_OFF + (size_t)D_ * D_;
constexpr size_t W2T_OFF = W1T_OFF + (size_t)64 * 1024;
constexpr size_t A1T_OFF = W2T_OFF + (size_t)64 * 1024;
constexpr size_t A2T_OFF = A1T_OFF + (size_t)64 * 1024;
constexpr size_t V1T_OFF = A2T_OFF + (size_t)64 * 1024;
constexpr size_t V2T_OFF = V1T_OFF + (size_t)32 * 1024;
constexpr size_t G1T_OFF = V2T_OFF + (size_t)32 * 1024;
constexpr size_t G2T_OFF = G1T_OFF + (size_t)160 * 1024;
constexpr size_t SCRATCH_FLOATS = G2T_OFF + (size_t)160 * 1024;

__device__ float g_scratch[SCRATCH_FLOATS];

// ---------------- helpers ----------------
__device__ __forceinline__ uint32_t tf32bits(float x) {
    uint32_t y;
    asm("cvt.rna.tf32.f32 %0, %1;" : "=r"(y) : "f"(x));
    return y;
}
__device__ __forceinline__ float tf32f(float x) {
    return __uint_as_float(tf32bits(x));
}
__device__ __forceinline__ void mma_tf32(float& c0, float& c1, float& c2, float& c3,
                                         uint32_t a0, uint32_t a1, uint32_t a2, uint32_t a3,
                                         uint32_t b0, uint32_t b1) {
    asm volatile(
        "mma.sync.aligned.m16n8k8.row.col.f32.tf32.tf32.f32 "
        "{%0,%1,%2,%3}, {%4,%5,%6,%7}, {%8,%9}, {%0,%1,%2,%3};"
        : "+f"(c0), "+f"(c1), "+f"(c2), "+f"(c3)
        : "r"(a0), "r"(a1), "r"(a2), "r"(a3), "r"(b0), "r"(b1));
}
__device__ __forceinline__ void ldsm_x4(uint32_t& r0, uint32_t& r1, uint32_t& r2,
                                        uint32_t& r3, uint32_t addr) {
    asm volatile("ldmatrix.sync.aligned.m8n8.x4.shared.b16 {%0,%1,%2,%3}, [%4];"
                 : "=r"(r0), "=r"(r1), "=r"(r2), "=r"(r3) : "r"(addr));
}
__device__ __forceinline__ void ldsm_x2(uint32_t& r0, uint32_t& r1, uint32_t addr) {
    asm volatile("ldmatrix.sync.aligned.m8n8.x2.shared.b16 {%0,%1}, [%2];"
                 : "=r"(r0), "=r"(r1) : "r"(addr));
}
__device__ __forceinline__ uint32_t smem_u32(const void* p) {
    uint32_t a;
    asm("{ .reg .u64 t; cvta.to.shared.u64 t, %1; cvt.u32.u64 %0, t; }"
        : "=r"(a) : "l"(p));
    return a;
}
__device__ __forceinline__ void cp_async16(uint32_t saddr, const void* gptr) {
    asm volatile("cp.async.cg.shared.global [%0], [%1], 16;"
                 :: "r"(saddr), "l"(gptr) : "memory");
}
__device__ __forceinline__ void cp_async16z(uint32_t saddr, const void* gptr, int valid) {
    asm volatile("cp.async.cg.shared.global [%0], [%1], 16, %2;"
                 :: "r"(saddr), "l"(gptr), "r"(valid ? 16 : 0) : "memory");
}
__device__ __forceinline__ void cp_commit() {
    asm volatile("cp.async.commit_group;" ::: "memory");
}
__device__ __forceinline__ void cp_wait1() {
    asm volatile("cp.async.wait_group 1;" ::: "memory");
}
__device__ __forceinline__ void cp_wait2g() {
    asm volatile("cp.async.wait_group 2;" ::: "memory");
}
__device__ __forceinline__ float apply_epi(float f, int mode,
                                           const float* __restrict__ bias, int colg) {
    if (mode == 1) {
        f = tanhf(f);
    } else if (mode == 2) {
        float s = 1.0f / (1.0f + expf(-(__ldg(&bias[colg]) + f)));
        f = expf(LOG_W_SCALE * s);
    } else if (mode == 3) {
        f = 1.0f / (1.0f + expf(-(__ldg(&bias[colg]) + f)));
    } else if (mode == 4) {
        f = 1.0f / (1.0f + expf(-f));
    }
    return f;
}

// ---------------- kernel: token-shift mixes, float4, tf32-rounded ----------------
__global__ void mix_kernel(const float4* __restrict__ x4,
                           const float4* __restrict__ xx4,
                           float4* __restrict__ out /* 6 x BTD/4 */) {
    size_t idx4 = (size_t)blockIdx.x * blockDim.x + threadIdx.x;
    if (idx4 >= BTD / 4) return;
    int d4 = (int)(idx4 & (D_ / 4 - 1));
    int t = (int)((idx4 >> 8) & (T_ - 1));
    float4 xc = x4[idx4];
    float4 xp = make_float4(0.f, 0.f, 0.f, 0.f);
    if (t > 0) xp = x4[idx4 - D_ / 4];
    float dx = xp.x - xc.x, dy = xp.y - xc.y, dz = xp.z - xc.z, dw = xp.w - xc.w;
#pragma unroll
    for (int j = 0; j < 6; j++) {
        float4 cf = __ldg(&xx4[j * (D_ / 4) + d4]);
        float4 r;
        r.x = tf32f(xc.x + dx * cf.x);
        r.y = tf32f(xc.y + dy * cf.y);
        r.z = tf32f(xc.z + dz * cf.z);
        r.w = tf32f(xc.w + dw * cf.w);
        out[(size_t)j * (BTD / 4) + idx4] = r;
    }
}

// ---------------- transpose kernel: in[K,N] -> out[N,K], tf32-rounded ----------------
__global__ void transpose_kernel(const float* __restrict__ in, float* __restrict__ out,
                                 int K, int N) {
    __shared__ float tile[32][33];
    int n0 = blockIdx.x * 32, k0 = blockIdx.y * 32;
    int tx = threadIdx.x, ty = threadIdx.y;  // 32 x 8
#pragma unroll
    for (int i = 0; i < 32; i += 8) {
        int k = k0 + ty + i, n = n0 + tx;
        if (k < K && n < N) tile[ty + i][tx] = tf32f(in[(size_t)k * N + n]);
    }
    __syncthreads();
#pragma unroll
    for (int i = 0; i < 32; i += 8) {
        int n = n0 + ty + i, k = k0 + tx;
        if (n < N && k < K) out[(size_t)n * K + k] = tile[tx][ty + i];
    }
}

// ---------------- tf32 GEMM: 3-stage cp.async, swizzled smem, 1 barrier/tile ----------------
constexpr int STAGE_FLOATS = 128 * 32;
constexpr unsigned GEMM_SMEM = 3 * 2 * STAGE_FLOATS * 4;     // 98304 B
__global__ __launch_bounds__(256)
void tgemm_kernel(const float* __restrict__ A, const float* __restrict__ Bt,
                  float* __restrict__ C, int M, int N, int K,
                  int mode, const float* __restrict__ bias, int rnd) {
    extern __shared__ float dsm[];
    uint32_t smem_base = smem_u32(dsm);

    int tid = threadIdx.x;
    int wid = tid >> 5, lane = tid & 31;
    int warp_m = wid >> 2;
    int warp_n = wid & 3;
    int gid = lane >> 2;
    int tig = lane & 3;
    int block_row = blockIdx.y * 128;
    int block_col = blockIdx.x * 128;

    float acc[4][4][4];
#pragma unroll
    for (int mt = 0; mt < 4; mt++)
#pragma unroll
        for (int nt = 0; nt < 4; nt++)
#pragma unroll
            for (int q = 0; q < 4; q++) acc[mt][nt][q] = 0.0f;

    int lr[4], lcc[4];
    uint32_t sdstA[4], sdstB[4];
#pragma unroll
    for (int i = 0; i < 4; i++) {
        int f4 = tid + i * 256;
        lr[i] = f4 >> 3;
        lcc[i] = f4 & 7;
        uint32_t sw = (uint32_t)(lcc[i] ^ (lr[i] & 7));
        sdstA[i] = (uint32_t)(lr[i] * 128 + sw * 16);
        sdstB[i] = sdstA[i] + STAGE_FLOATS * 4;
    }

    int ntiles = K >> 5;

    auto issue_tile = [&](int kt, int stage) {
        uint32_t sb = smem_base + (uint32_t)(stage * 2 * STAGE_FLOATS * 4);
        int k0 = kt << 5;
#pragma unroll
        for (int i = 0; i < 4; i++) {
            const float* ga = A + (size_t)(block_row + lr[i]) * K + k0 + lcc[i] * 4;
            cp_async16(sb + sdstA[i], ga);
            int rg = block_col + lr[i];
            const float* gb = Bt + (size_t)(rg < N ? rg : 0) * K + k0 + lcc[i] * 4;
            cp_async16z(sb + sdstB[i], gb, rg < N);
        }
    };

    issue_tile(0, 0);
    cp_commit();
    if (ntiles > 1) issue_tile(1, 1);
    cp_commit();

    int lr8 = lane & 7;
    uint32_t a_rowb[4], b_rowb[4];
#pragma unroll
    for (int mt = 0; mt < 4; mt++) {
        int ar = warp_m * 64 + mt * 16 + ((lane & 8) ? 8 : 0) + lr8;
        a_rowb[mt] = (uint32_t)(ar * 128);
    }
#pragma unroll
    for (int nt = 0; nt < 4; nt++) {
        int br = warp_n * 32 + nt * 8 + lr8;
        b_rowb[nt] = (uint32_t)(br * 128 + STAGE_FLOATS * 4);
    }
    uint32_t a_csel = (lane & 16) ? 1u : 0u;
    uint32_t b_csel = (lane & 8) ? 1u : 0u;
    uint32_t swmask = (uint32_t)lr8;

    for (int kt = 0; kt < ntiles; kt++) {
        cp_wait1();
        __syncthreads();

        int tn = kt + 2;
        if (tn < ntiles) issue_tile(tn, tn % 3);
        cp_commit();

        uint32_t sb = smem_base + (uint32_t)((kt % 3) * 2 * STAGE_FLOATS * 4);

#pragma unroll
        for (int ks = 0; ks < 4; ks++) {
            uint32_t af[4][4];
#pragma unroll
            for (int mt = 0; mt < 4; mt++) {
                uint32_t ch = ((uint32_t)(ks * 2) + a_csel) ^ swmask;
                ldsm_x4(af[mt][0], af[mt][1], af[mt][2], af[mt][3],
                        sb + a_rowb[mt] + ch * 16);
            }
            uint32_t bf[4][2];
#pragma unroll
            for (int nt = 0; nt < 4; nt++) {
                uint32_t ch = ((uint32_t)(ks * 2) + b_csel) ^ swmask;
                ldsm_x2(bf[nt][0], bf[nt][1], sb + b_rowb[nt] + ch * 16);
            }
#pragma unroll
            for (int mt = 0; mt < 4; mt++)
#pragma unroll
                for (int nt = 0; nt < 4; nt++)
                    mma_tf32(acc[mt][nt][0], acc[mt][nt][1], acc[mt][nt][2], acc[mt][nt][3],
                             af[mt][0], af[mt][1], af[mt][2], af[mt][3],
                             bf[nt][0], bf[nt][1]);
        }
    }

#pragma unroll
    for (int mt = 0; mt < 4; mt++) {
        int row = block_row + warp_m * 64 + mt * 16 + gid;
#pragma unroll
        for (int nt = 0; nt < 4; nt++) {
            int col0 = block_col + warp_n * 32 + nt * 8 + 2 * tig;
            if (col0 < N) {
                float2 v0, v1;
                v0.x = apply_epi(acc[mt][nt][0], mode, bias, col0);
                v0.y = apply_epi(acc[mt][nt][1], mode, bias, col0 + 1);
                v1.x = apply_epi(acc[mt][nt][2], mode, bias, col0);
                v1.y = apply_epi(acc[mt][nt][3], mode, bias, col0 + 1);
                if (rnd) {
                    v0.x = tf32f(v0.x); v0.y = tf32f(v0.y);
                    v1.x = tf32f(v1.x); v1.y = tf32f(v1.y);
                }
                *(float2*)(C + (size_t)row * N + col0) = v0;
                *(float2*)(C + (size_t)(row + 8) * N + col0) = v1;
            }
        }
    }
}

// ---------------- prep kernel ----------------
__global__ void prep_kernel(float* __restrict__ Kb, float* __restrict__ Vb,
                            const float* __restrict__ Ab, const float* __restrict__ VMIXb,
                            const float* __restrict__ vfirst,
                            const float* __restrict__ k_k, const float* __restrict__ k_a,
                            float* __restrict__ AKK, float* __restrict__ BKK) {
    int bt = blockIdx.x;
    int lane = threadIdx.x & 31;
    int h = threadIdx.x >> 5;
    int d0 = h * HD_ + lane, d1 = d0 + 32;
    size_t i0 = (size_t)bt * D_ + d0;
    size_t i1 = i0 + 32;

    float k0 = Kb[i0], k1 = Kb[i1];
    float kk0 = k0 * __ldg(&k_k[d0]);
    float kk1 = k1 * __ldg(&k_k[d1]);
    float ss = kk0 * kk0 + kk1 * kk1;
#pragma unroll
    for (int o = 16; o > 0; o >>= 1) ss += __shfl_xor_sync(0xffffffffu, ss, o);
    float inv = 1.0f / fmaxf(sqrtf(ss), 1e-12f);
    kk0 *= inv; kk1 *= inv;

    float a0v = Ab[i0], a1v = Ab[i1];
    AKK[i0] = -kk0;        AKK[i1] = -kk1;
    BKK[i0] = kk0 * a0v;   BKK[i1] = kk1 * a1v;

    Kb[i0] = k0 * (1.0f + (a0v - 1.0f) * __ldg(&k_a[d0]));
    Kb[i1] = k1 * (1.0f + (a1v - 1.0f) * __ldg(&k_a[d1]));

    float v0v = Vb[i0], v1v = Vb[i1];
    Vb[i0] = v0v + (vfirst[i0] - v0v) * VMIXb[i0];
    Vb[i1] = v1v + (vfirst[i1] - v1v) * VMIXb[i1];
}

// ---------------- scan kernel v12: 4-step groups, 16-slot ring, 1 wait/sync per group ----
// SC points at R; arrays at SC + arr*BTD: R(0) EW(1) K(2) V(3) AKK(4) BKK(5)
// grid = 512 blocks of 32 threads; block = (bh, quarter of 16 V-rows).
// lane: row = quar*16 + (lane>>1), k-half = lane&1 (32 k-cols), S[32] regs.
// Ring: 16 slots = 4 groups of 4; slot = t & 15. Refill t+12 -> group (t-4)'s slots.
__global__ __launch_bounds__(32)
void scan_kernel(const float* __restrict__ SC, float* __restrict__ O) {
    int bh = blockIdx.x >> 2;
    int quar = blockIdx.x & 3;
    int b = bh >> 4;
    int h = bh & 15;
    int lane = threadIdx.x;           // 0..31
    int i = quar * 16 + (lane >> 1);  // V row 0..63
    int cb = (lane & 1) * 32;         // k-col base

    __shared__ __align__(16) float ring[16][6][64];   // 24 KB

    float S[32];
#pragma unroll
    for (int k = 0; k < 32; k++) S[k] = 0.0f;

    size_t base = (size_t)b * T_ * D_ + (size_t)h * HD_;
    const unsigned FULL = 0xffffffffu;
    uint32_t rb = smem_u32(ring);

    // loader: 96 16B-chunks per step over 32 lanes (3 each)
    auto load_step = [&](int t, int slot) {
#pragma unroll
        for (int j = 0; j < 3; j++) {
            int ch = lane + j * 32;
            int a_ = ch >> 4;
            int e_ = (ch & 15) << 2;
            const float* g = SC + (size_t)a_ * BTD + base + (size_t)t * D_ + e_;
            cp_async16(rb + (uint32_t)(((slot * 6 + a_) * 64 + e_) * 4), g);
        }
    };

    // one scan step on ring slot s
    auto do_step = [&](int t, int s) {
        const float* vr = &ring[s][0][0];
        const float* vw = &ring[s][1][0];
        const float* vk = &ring[s][2][0];
        const float* vv = &ring[s][3][0];
        const float* va = &ring[s][4][0];
        const float* vb = &ring[s][5][0];

        float vi = vv[i];

        float sa0 = 0.f, sa1 = 0.f, sa2 = 0.f, sa3 = 0.f;
#pragma unroll
        for (int q = 0; q < 8; q++) {
            float4 a4 = *(const float4*)(va + cb + q * 4);
            sa0 = fmaf(S[q * 4 + 0], a4.x, sa0);
            sa1 = fmaf(S[q * 4 + 1], a4.y, sa1);
            sa2 = fmaf(S[q * 4 + 2], a4.z, sa2);
            sa3 = fmaf(S[q * 4 + 3], a4.w, sa3);
        }
        float sa = (sa0 + sa1) + (sa2 + sa3);
        sa += __shfl_xor_sync(FULL, sa, 1);

        float o0 = 0.f, o1 = 0.f, o2 = 0.f, o3 = 0.f;
#pragma unroll
        for (int q = 0; q < 8; q++) {
            float4 w4 = *(const float4*)(vw + cb + q * 4);
            float4 k4 = *(const float4*)(vk + cb + q * 4);
            float4 b4 = *(const float4*)(vb + cb + q * 4);
            float4 r4 = *(const float4*)(vr + cb + q * 4);
            S[q * 4 + 0] = fmaf(S[q * 4 + 0], w4.x, fmaf(sa, b4.x, vi * k4.x));
            S[q * 4 + 1] = fmaf(S[q * 4 + 1], w4.y, fmaf(sa, b4.y, vi * k4.y));
            S[q * 4 + 2] = fmaf(S[q * 4 + 2], w4.z, fmaf(sa, b4.z, vi * k4.z));
            S[q * 4 + 3] = fmaf(S[q * 4 + 3], w4.w, fmaf(sa, b4.w, vi * k4.w));
            o0 = fmaf(S[q * 4 + 0], r4.x, o0);
            o1 = fmaf(S[q * 4 + 1], r4.y, o1);
            o2 = fmaf(S[q * 4 + 2], r4.z, o2);
            o3 = fmaf(S[q * 4 + 3], r4.w, o3);
        }
        float op = (o0 + o1) + (o2 + o3);
        op += __shfl_xor_sync(FULL, op, 1);
        if ((lane & 1) == 0) O[base + (size_t)t * D_ + i] = op;
    };

    // prologue: groups for steps 0..3, 4..7, 8..11 (3 committed groups)
#pragma unroll
    for (int gidx = 0; gidx < 3; gidx++) {
#pragma unroll
        for (int j = 0; j < 4; j++)
            load_step(gidx * 4 + j, gidx * 4 + j);
        cp_commit();
    }

    for (int t = 0; t < T_; t += 4) {
        cp_wait2g();       // group(t) landed (<=2 younger groups outstanding)
        __syncwarp();      // all lanes past group(t-4) reads

        // refill group(t+12) into group(t-4)'s slots ((t+12) & 15 == (t-4) & 15)
        int tn = t + 12;
        if (tn < T_) {
#pragma unroll
            for (int j = 0; j < 4; j++)
                load_step(tn + j, (tn + j) & 15);
        }
        cp_commit();

        do_step(t,     t & 15);
        do_step(t + 1, (t + 1) & 15);
        do_step(t + 2, (t + 2) & 15);
        do_step(t + 3, (t + 3) & 15);
    }
}

// ---------------- post kernel: groupnorm + bonus + gate (tf32-rounded out) ----------------
__global__ void post_kernel(const float* __restrict__ O, const float* __restrict__ R,
                            const float* __restrict__ Kb, const float* __restrict__ Vb,
                            const float* __restrict__ G, const float* __restrict__ r_k,
                            const float* __restrict__ gn_w, const float* __restrict__ gn_b,
                            float* __restrict__ GATED) {
    int bt = blockIdx.x;
    int lane = threadIdx.x & 31;
    int h = threadIdx.x >> 5;
    int d0 = h * HD_ + lane, d1 = d0 + 32;
    size_t i0 = (size_t)bt * D_ + d0;
    size_t i1 = i0 + 32;

    float o0 = O[i0], o1 = O[i1];
    float s = o0 + o1;
    float sq = o0 * o0 + o1 * o1;
    float dot = R[i0] * Kb[i0] * __ldg(&r_k[d0]) + R[i1] * Kb[i1] * __ldg(&r_k[d1]);
#pragma unroll
    for (int o = 16; o > 0; o >>= 1) {
        s   += __shfl_xor_sync(0xffffffffu, s, o);
        sq  += __shfl_xor_sync(0xffffffffu, sq, o);
        dot += __shfl_xor_sync(0xffffffffu, dot, o);
    }
    float mean = s * (1.0f / 64.0f);
    float var = sq * (1.0f / 64.0f) - mean * mean;
    float rstd = rsqrtf(var + GN_EPS);
    float on0 = (o0 - mean) * rstd * __ldg(&gn_w[d0]) + __ldg(&gn_b[d0]);
    float on1 = (o1 - mean) * rstd * __ldg(&gn_w[d1]) + __ldg(&gn_b[d1]);
    on0 += dot * Vb[i0];
    on1 += dot * Vb[i1];
    GATED[i0] = tf32f(on0 * G[i0]);
    GATED[i1] = tf32f(on1 * G[i1]);
}

// ---------------- host launchers ----------------
static void run_tgemm(const float* A, const float* Bt, float* C,
                      int M, int N, int K, int mode, const float* bias, int rnd) {
    dim3 grid((N + 127) / 128, M / 128);
    tgemm_kernel<<<grid, 256, GEMM_SMEM>>>(A, Bt, C, M, N, K, mode, bias, rnd);
}
static void run_transpose(const float* in, float* out, int K, int N) {
    dim3 grid((N + 31) / 32, (K + 31) / 32);
    transpose_kernel<<<grid, dim3(32, 8)>>>(in, out, K, N);
}

extern "C" void kernel_launch(void* const* d_in, const int* in_sizes, int n_in,
                              void* d_out, int out_size) {
    const float* x       = (const float*)d_in[0];
    const float* v_first = (const float*)d_in[1];
    const float* x_x     = (const float*)d_in[2];
    const float* W_r     = (const float*)d_in[3];
    const float* W_k     = (const float*)d_in[4];
    const float* W_v     = (const float*)d_in[5];
    const float* W_o     = (const float*)d_in[6];
    const float* w1      = (const float*)d_in[7];
    const float* w2      = (const float*)d_in[8];
    const float* w0      = (const float*)d_in[9];
    const float* a1      = (const float*)d_in[10];
    const float* a2      = (const float*)d_in[11];
    const float* a0      = (const float*)d_in[12];
    const float* v1      = (const float*)d_in[13];
    const float* v2      = (const float*)d_in[14];
    const float* v0      = (const float*)d_in[15];
    const float* g1      = (const float*)d_in[16];
    const float* g2      = (const float*)d_in[17];
    const float* k_k     = (const float*)d_in[18];
    const float* k_a     = (const float*)d_in[19];
    const float* r_k     = (const float*)d_in[20];
    const float* gn_w    = (const float*)d_in[21];
    const float* gn_b    = (const float*)d_in[22];
    float* out = (float*)d_out;

    static bool attr_done = false;
    if (!attr_done) {
        cudaFuncSetAttribute(tgemm_kernel,
                             cudaFuncAttributeMaxDynamicSharedMemorySize, GEMM_SMEM);
        attr_done = true;
    }

    float* sc;
    cudaGetSymbolAddress((void**)&sc, g_scratch);

    float* XR    = sc + 0 * BTD;
    float* XW    = sc + 1 * BTD;
    float* XK    = sc + 2 * BTD;
    float* XV    = sc + 3 * BTD;
    float* XA    = sc + 4 * BTD;
    float* XG    = sc + 5 * BTD;
    float* Rb    = sc + 6 * BTD;
    float* EWb   = sc + 7 * BTD;
    float* Kb    = sc + 8 * BTD;
    float* Vb    = sc + 9 * BTD;
    float* AKKb  = sc + 10 * BTD;
    float* BKKb  = sc + 11 * BTD;
    float* Ab    = sc + 12 * BTD;
    float* VMIXb = sc + 13 * BTD;
    float* Ob    = sc + 14 * BTD;
    float* Gb    = sc + 15 * BTD;
    float* GATED = sc + 16 * BTD;
    float* T1b   = sc + T1_OFF;
    float* T2b   = sc + T2_OFF;
    float* T3b   = sc + T3_OFF;
    float* T4b   = sc + T4_OFF;
    float* WRT   = sc + WRT_OFF;
    float* WKT   = sc + WKT_OFF;
    float* WVT   = sc + WVT_OFF;
    float* WOT   = sc + WOT_OFF;
    float* W1T   = sc + W1T_OFF;
    float* W2T   = sc + W2T_OFF;
    float* A1T   = sc + A1T_OFF;
    float* A2T   = sc + A2T_OFF;
    float* V1T   = sc + V1T_OFF;
    float* V2T   = sc + V2T_OFF;
    float* G1T   = sc + G1T_OFF;
    float* G2T   = sc + G2T_OFF;

    mix_kernel<<<(unsigned)((BTD / 4 + 255) / 256), 256>>>(
        (const float4*)x, (const float4*)x_x, (float4*)XR);
    run_transpose(W_r, WRT, D_, D_);
    run_transpose(W_k, WKT, D_, D_);
    run_tgemm(XR, WRT, Rb, (int)BT, D_, D_, 0, nullptr, 0);
    run_tgemm(XK, WKT, Kb, (int)BT, D_, D_, 0, nullptr, 0);
    run_transpose(W_v, WVT, D_, D_);
    run_tgemm(XV, WVT, Vb, (int)BT, D_, D_, 0, nullptr, 0);

    run_transpose(W_o, WOT, D_, D_);
    run_transpose(w1, W1T, D_, 64);
    run_transpose(w2, W2T, 64, D_);
    run_transpose(a1, A1T, D_, 64);
    run_transpose(a2, A2T, 64, D_);
    run_transpose(v1, V1T, D_, 32);
    run_transpose(v2, V2T, 32, D_);
    run_transpose(g1, G1T, D_, 160);
    run_transpose(g2, G2T, 160, D_);

    // low-rank chains
    run_tgemm(XW, W1T, T1b, (int)BT, 64, D_, 1, nullptr, 1);
    run_tgemm(T1b, W2T, EWb, (int)BT, D_, 64, 2, w0, 0);
    run_tgemm(XA, A1T, T2b, (int)BT, 64, D_, 0, nullptr, 1);
    run_tgemm(T2b, A2T, Ab, (int)BT, D_, 64, 3, a0, 0);
    run_tgemm(XV, V1T, T3b, (int)BT, 32, D_, 0, nullptr, 1);
    run_tgemm(T3b, V2T, VMIXb, (int)BT, D_, 32, 3, v0, 0);
    run_tgemm(XG, G1T, T4b, (int)BT, 160, D_, 4, nullptr, 1);
    run_tgemm(T4b, G2T, Gb, (int)BT, D_, 160, 0, nullptr, 0);

    // prep
    prep_kernel<<<(unsigned)BT, 512>>>(Kb, Vb, Ab, VMIXb, v_first, k_k, k_a, AKKb, BKKb);

    // sequential scan (4 warps per (b,h), warp-autonomous, k-split x2, 4-step groups)
    scan_kernel<<<4 * B_ * H_, 32>>>(Rb, Ob);

    // groupnorm + bonus + gate
    post_kernel<<<(unsigned)BT, 512>>>(Ob, Rb, Kb, Vb, Gb, r_k, gn_w, gn_b, GATED);

    // output projection
    run_tgemm(GATED, WOT, out, (int)BT, D_, D_, 0, nullptr, 0);

    // v_first passthrough
    if ((size_t)out_size >= 2 * BTD) {
        cudaMemcpyAsync(out + BTD, v_first, BTD * sizeof(float),
                        cudaMemcpyDeviceToDevice, 0);
    }
}